// round 14
// baseline (speedup 1.0000x reference)
#include <cuda_runtime.h>
#include <cuda_bf16.h>
#include <math.h>
#include <stdint.h>

#define TDEC 250
#define BATCH 128
#define TENC 1024
#define NT 512

// keys^T: [b][d][t], bf16
__device__ __nv_bfloat16 g_keysT[BATCH * 256 * TENC];

__device__ __forceinline__ float tanh_fast(float x) {
    float y;
    asm("tanh.approx.f32 %0, %1;" : "=f"(y) : "f"(x));
    return y;
}

__global__ void zero_wp(float* wp) {
    int i = blockIdx.x * blockDim.x + threadIdx.x;
    if (i < TDEC) wp[i] = 0.f;
}

// keys^T = (enc @ Wk + bk)^T per batch row, bf16, coalesced via smem staging
__global__ void keys_gemm(const float* __restrict__ A, const float* __restrict__ B,
                          const float* __restrict__ bias, __nv_bfloat16* __restrict__ C)
{
    __shared__ float As[16][64], Bs[16][64];
    __shared__ __nv_bfloat16 Ts[64][72];
    int tid = threadIdx.x;
    int n0 = blockIdx.x * 64, m0 = blockIdx.y * 64;
    int tm0 = (tid >> 4) * 4, tn0 = (tid & 15) * 4;
    float acc[4][4];
#pragma unroll
    for (int i = 0; i < 4; i++)
#pragma unroll
        for (int j = 0; j < 4; j++) acc[i][j] = 0.f;
    int arow = tid >> 2, akc = (tid & 3) * 4;
    int brow = tid >> 4, bnc = (tid & 15) * 4;
    for (int k0 = 0; k0 < 256; k0 += 16) {
        float4 av = *(const float4*)(A + (size_t)(m0 + arow) * 256 + k0 + akc);
        float4 bv = *(const float4*)(B + (size_t)(k0 + brow) * 256 + n0 + bnc);
        __syncthreads();
        As[akc + 0][arow] = av.x; As[akc + 1][arow] = av.y;
        As[akc + 2][arow] = av.z; As[akc + 3][arow] = av.w;
        *(float4*)&Bs[brow][bnc] = bv;
        __syncthreads();
#pragma unroll
        for (int kk = 0; kk < 16; kk++) {
            float4 a4 = *(float4*)&As[kk][tm0];
            float4 b4 = *(float4*)&Bs[kk][tn0];
            float ar[4] = {a4.x, a4.y, a4.z, a4.w};
            float br[4] = {b4.x, b4.y, b4.z, b4.w};
#pragma unroll
            for (int i = 0; i < 4; i++)
#pragma unroll
                for (int j = 0; j < 4; j++)
                    acc[i][j] = fmaf(ar[i], br[j], acc[i][j]);
        }
    }
    __syncthreads();
    // stage transposed: Ts[d_local][t_local]
#pragma unroll
    for (int i = 0; i < 4; i++)
#pragma unroll
        for (int j = 0; j < 4; j++)
            Ts[tn0 + j][tm0 + i] = __float2bfloat16(acc[i][j] + bias[n0 + tn0 + j]);
    __syncthreads();
    int b = m0 >> 10;
    int t0 = m0 & 1023;
#pragma unroll
    for (int p = 0; p < 4; p++) {
        int dl = (tid >> 4) + p * 16;
        int t4 = (tid & 15) * 4;
        uint2 v = *(uint2*)&Ts[dl][t4];
        *(uint2*)(C + ((size_t)b * 256 + n0 + dl) * 1024 + t0 + t4) = v;
    }
}

// ---- vec-mat, 2 rows, float4 weights, K-split; partial-combine via pbuf ----
// ACT: 0 none, 1 relu, 2 sigmoid(expf), 3 tanhf    (requires K % SPLIT == 0)
template<int K, int N, int SPLIT, int ACT>
__device__ __forceinline__ void vm4(const float* __restrict__ W,
                                    const float* __restrict__ bias,
                                    const float* x0, const float* x1,
                                    float* y0, float* y1, float* pbuf)
{
    constexpr int NG = N / 4;
    constexpr int KP = K / SPLIT;
    static_assert(KP * SPLIT == K, "SPLIT must divide K");
    const int tid = threadIdx.x;
    const int g = tid % NG;
    const int h = tid / NG;
    float4* pb = (float4*)pbuf;
    if (h < SPLIT) {
        const float4* w4 = (const float4*)W + g;
        float a00 = 0.f, a01 = 0.f, a02 = 0.f, a03 = 0.f;
        float a10 = 0.f, a11 = 0.f, a12 = 0.f, a13 = 0.f;
        const int k0 = h * KP;
#pragma unroll 4
        for (int k = k0; k < k0 + KP; k++) {
            float4 w = w4[(size_t)k * NG];
            float xa = x0[k], xb = x1[k];
            a00 = fmaf(xa, w.x, a00); a01 = fmaf(xa, w.y, a01);
            a02 = fmaf(xa, w.z, a02); a03 = fmaf(xa, w.w, a03);
            a10 = fmaf(xb, w.x, a10); a11 = fmaf(xb, w.y, a11);
            a12 = fmaf(xb, w.z, a12); a13 = fmaf(xb, w.w, a13);
        }
        pb[(h * 2 + 0) * NG + g] = make_float4(a00, a01, a02, a03);
        pb[(h * 2 + 1) * NG + g] = make_float4(a10, a11, a12, a13);
    }
    __syncthreads();
    for (int idx = tid; idx < 2 * NG; idx += NT) {
        int r = (idx >= NG) ? 1 : 0;
        int gg = idx - r * NG;
        float4 s = pb[gg + r * NG];
#pragma unroll
        for (int hh = 1; hh < SPLIT; hh++) {
            float4 p = pb[(hh * 2 + r) * NG + gg];
            s.x += p.x; s.y += p.y; s.z += p.z; s.w += p.w;
        }
        float4 b4 = ((const float4*)bias)[gg];
        s.x += b4.x; s.y += b4.y; s.z += b4.z; s.w += b4.w;
        if (ACT == 1) {
            s.x = fmaxf(s.x, 0.f); s.y = fmaxf(s.y, 0.f);
            s.z = fmaxf(s.z, 0.f); s.w = fmaxf(s.w, 0.f);
        } else if (ACT == 2) {
            s.x = 1.f / (1.f + expf(-s.x)); s.y = 1.f / (1.f + expf(-s.y));
            s.z = 1.f / (1.f + expf(-s.z)); s.w = 1.f / (1.f + expf(-s.w));
        } else if (ACT == 3) {
            s.x = tanhf(s.x); s.y = tanhf(s.y);
            s.z = tanhf(s.z); s.w = tanhf(s.w);
        }
        float* yy = r ? y1 : y0;
        ((float4*)yy)[gg] = s;
    }
    __syncthreads();
}

// ------------------- persistent decoder: 1 block = 2 batch rows ------------
__global__ void __launch_bounds__(NT, 1) decode_kernel(
    const float* __restrict__ enc, const int* __restrict__ mask,
    const float* __restrict__ inp_att, const float* __restrict__ style_tok,
    const float* __restrict__ pre_W1, const float* __restrict__ pre_b1,
    const float* __restrict__ pre_W2, const float* __restrict__ pre_b2,
    const float* __restrict__ att_Wg, const float* __restrict__ att_bg,
    const float* __restrict__ att_Wc, const float* __restrict__ att_bc,
    const float* __restrict__ attn_Wq, const float* __restrict__ attn_bq,
    const float* __restrict__ attn_v,
    const float* __restrict__ deci_W, const float* __restrict__ deci_b,
    const float* __restrict__ dec1_Wg, const float* __restrict__ dec1_bg,
    const float* __restrict__ dec1_Wc, const float* __restrict__ dec1_bc,
    const float* __restrict__ dec2_Wg, const float* __restrict__ dec2_bg,
    const float* __restrict__ dec2_Wc, const float* __restrict__ dec2_bc,
    const float* __restrict__ out_W, const float* __restrict__ out_b,
    float* __restrict__ seq, float* __restrict__ alph, float* __restrict__ wp)
{
    extern __shared__ float sm[];
    float (*es)[1024] = (float(*)[1024])sm;                 // 2048
    float (*xa)[640]  = (float(*)[640])(sm + 2048);         // 1280
    float (*xd)[512]  = (float(*)[512])(sm + 3328);         // 1024
    float (*x1)[512]  = (float(*)[512])(sm + 4352);         // 1024
    float (*x2)[512]  = (float(*)[512])(sm + 5376);         // 1024
    float (*tmp)[512] = (float(*)[512])(sm + 6400);         // 1024
    float (*hA)[256]  = (float(*)[256])(sm + 7424);         // 512
    float (*h1s)[256] = (float(*)[256])(sm + 7936);
    float (*h2s)[256] = (float(*)[256])(sm + 8448);
    float (*us)[256]  = (float(*)[256])(sm + 8960);
    float (*sst)[256] = (float(*)[256])(sm + 9472);
    float (*lastv)[80] = (float(*)[80])(sm + 9984);         // 160
    float* vsh = sm + 10144;                                // 256
    float (*red)[8] = (float(*)[8])(sm + 10400);            // 16
    float* pbuf = sm + 10416;                               // 4096  -> 14512 total

    const int tid = threadIdx.x;
    const int blk = blockIdx.x;
    const int r8 = tid >> 8;
    const int d8 = tid & 255;

    if (tid < 256) vsh[tid] = attn_v[tid];
    {
        int b = blk * 2 + r8;
        float s = 0.f;
#pragma unroll
        for (int k = 0; k < 10; k++)
            s += inp_att[b * 10 + k] * style_tok[k * 256 + d8];
        sst[r8][d8] = s;
        hA[r8][d8] = 0.f; h1s[r8][d8] = 0.f; h2s[r8][d8] = 0.f;
        xa[r8][d8] = 0.f;
        if (d8 < 80) lastv[r8][d8] = 0.f;
    }
    __syncthreads();

    const int mb0 = mask[blk * 2], mb1 = mask[blk * 2 + 1];
    const int lane = tid & 31;
    const int rr = r8;
    const int wl = (tid >> 5) & 7;
    const int lt = d8;
    const int mbr = rr ? mb1 : mb0;
    const size_t browg = (size_t)(blk * 2 + rr);

    for (int t = 0; t < TDEC; t++) {
        // S1: p1 = relu(last @ W1 + b1) -> x1[:256)   (SPLIT=8: 80/8=10)
        vm4<80, 256, 8, 1>(pre_W1, pre_b1, lastv[0], lastv[1], x1[0], x1[1], pbuf);
        // S2: p = relu(p1 @ W2 + b2) -> xa[256:384)
        vm4<256, 128, 16, 1>(pre_W2, pre_b2, x1[0], x1[1], xa[0] + 256, xa[1] + 256, pbuf);
        // h_att -> xa[384:640)
        xa[r8][384 + d8] = hA[r8][d8];
        __syncthreads();
        // S3: gates = sigmoid([ctx,p,h] @ att_Wg + bg)
        vm4<640, 512, 4, 2>(att_Wg, att_bg, xa[0], xa[1], tmp[0], tmp[1], pbuf);
        xa[r8][384 + d8] = tmp[r8][d8] * hA[r8][d8];
        us[r8][d8] = tmp[r8][256 + d8];
        __syncthreads();
        // S4: c = tanh([ctx,p,r*h] @ att_Wc + bc); h_att = u*h + (1-u)*c
        vm4<640, 256, 8, 3>(att_Wc, att_bc, xa[0], xa[1], tmp[0], tmp[1], pbuf);
        {
            float u = us[r8][d8];
            float hn = u * hA[r8][d8] + (1.f - u) * tmp[r8][d8];
            hA[r8][d8] = hn;
            xd[r8][d8] = hn;
        }
        __syncthreads();
        // S5: q = h_att @ Wq + bq -> x2[:256)
        vm4<256, 256, 8, 0>(attn_Wq, attn_bq, hA[0], hA[1], x2[0], x2[1], pbuf);

        // ---- S6: attention ----
        {
            const int t4 = lt * 4;
            if (t4 < mbr) {
                const __nv_bfloat16* kb = g_keysT + browg * 256 * 1024 + t4;
                const float* qs = x2[rr];
                float e0 = 0.f, e1 = 0.f, e2 = 0.f, e3 = 0.f;
#pragma unroll 8
                for (int d = 0; d < 256; d++) {
                    uint2 kv = *(const uint2*)(kb + (size_t)d * 1024);
                    float2 f0 = __bfloat1622float2(*(__nv_bfloat162*)&kv.x);
                    float2 f1 = __bfloat1622float2(*(__nv_bfloat162*)&kv.y);
                    float q = qs[d], v = vsh[d];
                    e0 = fmaf(tanh_fast(f0.x + q), v, e0);
                    e1 = fmaf(tanh_fast(f0.y + q), v, e1);
                    e2 = fmaf(tanh_fast(f1.x + q), v, e2);
                    e3 = fmaf(tanh_fast(f1.y + q), v, e3);
                }
                es[rr][t4 + 0] = e0;
                es[rr][t4 + 1] = e1;
                es[rr][t4 + 2] = e2;
                es[rr][t4 + 3] = e3;
            }
            __syncthreads();
            // softmax over [0, mbr), 256 threads per row
            float mx = -1e30f;
            for (int tt = lt; tt < mbr; tt += 256) mx = fmaxf(mx, es[rr][tt]);
#pragma unroll
            for (int o = 16; o; o >>= 1)
                mx = fmaxf(mx, __shfl_xor_sync(0xffffffffu, mx, o));
            if (lane == 0) red[rr][wl] = mx;
            __syncthreads();
            mx = red[rr][0];
#pragma unroll
            for (int i = 1; i < 8; i++) mx = fmaxf(mx, red[rr][i]);
            float smv = 0.f;
            for (int tt = lt; tt < mbr; tt += 256) {
                float p = __expf(es[rr][tt] - mx);
                es[rr][tt] = p;
                smv += p;
            }
#pragma unroll
            for (int o = 16; o; o >>= 1)
                smv += __shfl_xor_sync(0xffffffffu, smv, o);
            __syncthreads();
            if (lane == 0) red[rr][wl] = smv;
            __syncthreads();
            float tsum = red[rr][0];
#pragma unroll
            for (int i = 1; i < 8; i++) tsum += red[rr][i];
            float inv = 1.f / tsum;
            float* arow = alph + ((size_t)t * BATCH + browg) * 1024;
            for (int tt = lt; tt < 1024; tt += 256) {
                float a = (tt < mbr) ? es[rr][tt] * inv : 0.f;
                es[rr][tt] = a;
                arow[tt] = a;
            }
            __syncthreads();
            // context: thread lt owns dim lt; 4 accumulators, deep MLP
            const float* erow = enc + browg * TENC * 256 + lt;
            float c0 = 0.f, c1 = 0.f, c2 = 0.f, c3 = 0.f;
            int tt = 0;
#pragma unroll 4
            for (; tt + 3 < mbr; tt += 4) {
                c0 = fmaf(es[rr][tt + 0], erow[(size_t)(tt + 0) * 256], c0);
                c1 = fmaf(es[rr][tt + 1], erow[(size_t)(tt + 1) * 256], c1);
                c2 = fmaf(es[rr][tt + 2], erow[(size_t)(tt + 2) * 256], c2);
                c3 = fmaf(es[rr][tt + 3], erow[(size_t)(tt + 3) * 256], c3);
            }
            for (; tt < mbr; tt++)
                c0 = fmaf(es[rr][tt], erow[(size_t)tt * 256], c0);
            float c = (c0 + c1) + (c2 + c3);
            xa[rr][lt] = c;
            xd[rr][256 + lt] = c + sst[rr][lt];
            float as_ = fabsf(sst[rr][lt]);
            float f = as_ / (fabsf(c) + as_);
#pragma unroll
            for (int o = 16; o; o >>= 1)
                f += __shfl_xor_sync(0xffffffffu, f, o);
            __syncthreads();
            if (lane == 0) red[rr][wl] = f;
            __syncthreads();
            if (tid == 0) {
                float s = 0.f;
#pragma unroll
                for (int i = 0; i < 8; i++) s += red[0][i] + red[1][i];
                atomicAdd(wp + t, s * (1.f / (BATCH * 256.f)));
            }
            __syncthreads();
        }

        // S7: dec_in = [h_att, wctx] @ deci_W + b -> x1[:256)
        vm4<512, 256, 8, 0>(deci_W, deci_b, xd[0], xd[1], x1[0], x1[1], pbuf);
        x1[r8][256 + d8] = h1s[r8][d8];
        __syncthreads();
        // S8: dec1 gates
        vm4<512, 512, 4, 2>(dec1_Wg, dec1_bg, x1[0], x1[1], tmp[0], tmp[1], pbuf);
        x1[r8][256 + d8] = tmp[r8][d8] * h1s[r8][d8];
        us[r8][d8] = tmp[r8][256 + d8];
        __syncthreads();
        // S9: dec1 cand; h1 update; o1 = h1 + dec_in -> x2[:256)
        vm4<512, 256, 8, 3>(dec1_Wc, dec1_bc, x1[0], x1[1], tmp[0], tmp[1], pbuf);
        {
            float u = us[r8][d8];
            float hn = u * h1s[r8][d8] + (1.f - u) * tmp[r8][d8];
            h1s[r8][d8] = hn;
            x2[r8][d8] = hn + x1[r8][d8];
            x2[r8][256 + d8] = h2s[r8][d8];
        }
        __syncthreads();
        // S10: dec2 gates
        vm4<512, 512, 4, 2>(dec2_Wg, dec2_bg, x2[0], x2[1], tmp[0], tmp[1], pbuf);
        x2[r8][256 + d8] = tmp[r8][d8] * h2s[r8][d8];
        us[r8][d8] = tmp[r8][256 + d8];
        __syncthreads();
        // S11: dec2 cand; h2 update; o2 = h2 + o1 -> x1[:256)
        vm4<512, 256, 8, 3>(dec2_Wc, dec2_bc, x2[0], x2[1], tmp[0], tmp[1], pbuf);
        {
            float u = us[r8][d8];
            float hn = u * h2s[r8][d8] + (1.f - u) * tmp[r8][d8];
            h2s[r8][d8] = hn;
            x1[r8][d8] = hn + x2[r8][d8];
        }
        __syncthreads();
        // S12: dense_out = o2 @ out_W + out_b (N=400)
        vm4<256, 400, 4, 0>(out_W, out_b, x1[0], x1[1], tmp[0], tmp[1], pbuf);
        if (tid < 400) {
#pragma unroll
            for (int r = 0; r < 2; r++) {
                float v = tmp[r][tid];
                seq[(size_t)(blk * 2 + r) * (TDEC * 400) + t * 400 + tid] = v;
                if (tid >= 320) lastv[r][tid - 320] = v;
            }
        }
        __syncthreads();
    }
}

extern "C" void kernel_launch(void* const* d_in, const int* in_sizes, int n_in,
                              void* d_out, int out_size)
{
    const float* enc      = (const float*)d_in[0];
    const int*   mask     = (const int*)d_in[1];
    const float* inp_att  = (const float*)d_in[2];
    const float* style_tk = (const float*)d_in[3];
    const float* pre_W1   = (const float*)d_in[4];
    const float* pre_b1   = (const float*)d_in[5];
    const float* pre_W2   = (const float*)d_in[6];
    const float* pre_b2   = (const float*)d_in[7];
    const float* att_Wg   = (const float*)d_in[8];
    const float* att_bg   = (const float*)d_in[9];
    const float* att_Wc   = (const float*)d_in[10];
    const float* att_bc   = (const float*)d_in[11];
    const float* attn_Wk  = (const float*)d_in[12];
    const float* attn_bk  = (const float*)d_in[13];
    const float* attn_Wq  = (const float*)d_in[14];
    const float* attn_bq  = (const float*)d_in[15];
    const float* attn_v   = (const float*)d_in[16];
    const float* deci_W   = (const float*)d_in[17];
    const float* deci_b   = (const float*)d_in[18];
    const float* dec1_Wg  = (const float*)d_in[19];
    const float* dec1_bg  = (const float*)d_in[20];
    const float* dec1_Wc  = (const float*)d_in[21];
    const float* dec1_bc  = (const float*)d_in[22];
    const float* dec2_Wg  = (const float*)d_in[23];
    const float* dec2_bg  = (const float*)d_in[24];
    const float* dec2_Wc  = (const float*)d_in[25];
    const float* dec2_bc  = (const float*)d_in[26];
    const float* out_W    = (const float*)d_in[27];
    const float* out_b    = (const float*)d_in[28];

    float* out  = (float*)d_out;
    float* seq  = out;
    float* alph = out + (size_t)BATCH * TDEC * 5 * 80;
    float* wp   = alph + (size_t)TDEC * BATCH * TENC;

    __nv_bfloat16* pKeysT;
    cudaGetSymbolAddress((void**)&pKeysT, g_keysT);

    static int smem_set = 0;
    const int smem_bytes = 14512 * 4;
    if (!smem_set) {
        cudaFuncSetAttribute(decode_kernel,
                             cudaFuncAttributeMaxDynamicSharedMemorySize, smem_bytes);
        smem_set = 1;
    }

    zero_wp<<<1, 256>>>(wp);
    keys_gemm<<<dim3(4, 2048), 256>>>(enc, attn_Wk, attn_bk, pKeysT);
    decode_kernel<<<BATCH / 2, NT, smem_bytes>>>(
        enc, mask, inp_att, style_tk,
        pre_W1, pre_b1, pre_W2, pre_b2,
        att_Wg, att_bg, att_Wc, att_bc,
        attn_Wq, attn_bq, attn_v,
        deci_W, deci_b,
        dec1_Wg, dec1_bg, dec1_Wc, dec1_bc,
        dec2_Wg, dec2_bg, dec2_Wc, dec2_bc,
        out_W, out_b,
        seq, alph, wp);
}

// round 15
// speedup vs baseline: 1.1091x; 1.1091x over previous
#include <cuda_runtime.h>
#include <cuda_bf16.h>
#include <math.h>
#include <stdint.h>

#define TDEC 250
#define BATCH 128
#define TENC 1024
#define NT 512

__device__ __nv_bfloat16 g_keys[BATCH * TENC * 256];   // enc @ Wk + bk (bf16)

__device__ __forceinline__ float tanh_fast(float x) {
    float y;
    asm("tanh.approx.f32 %0, %1;" : "=f"(y) : "f"(x));
    return y;
}

__global__ void zero_wp(float* wp) {
    int i = blockIdx.x * blockDim.x + threadIdx.x;
    if (i < TDEC) wp[i] = 0.f;
}

// ---------------- keys = enc(131072x256) @ Wk + bk  -> bf16 ----------------
__global__ void keys_gemm(const float* __restrict__ A, const float* __restrict__ B,
                          const float* __restrict__ bias, __nv_bfloat16* __restrict__ C)
{
    __shared__ float As[16][64], Bs[16][64];
    int tid = threadIdx.x;
    int n0 = blockIdx.x * 64, m0 = blockIdx.y * 64;
    int tm0 = (tid >> 4) * 4, tn0 = (tid & 15) * 4;
    float acc[4][4];
#pragma unroll
    for (int i = 0; i < 4; i++)
#pragma unroll
        for (int j = 0; j < 4; j++) acc[i][j] = 0.f;
    int arow = tid >> 2, akc = (tid & 3) * 4;
    int brow = tid >> 4, bnc = (tid & 15) * 4;
    for (int k0 = 0; k0 < 256; k0 += 16) {
        float4 av = *(const float4*)(A + (size_t)(m0 + arow) * 256 + k0 + akc);
        float4 bv = *(const float4*)(B + (size_t)(k0 + brow) * 256 + n0 + bnc);
        __syncthreads();
        As[akc + 0][arow] = av.x; As[akc + 1][arow] = av.y;
        As[akc + 2][arow] = av.z; As[akc + 3][arow] = av.w;
        *(float4*)&Bs[brow][bnc] = bv;
        __syncthreads();
#pragma unroll
        for (int kk = 0; kk < 16; kk++) {
            float4 a4 = *(float4*)&As[kk][tm0];
            float4 b4 = *(float4*)&Bs[kk][tn0];
            float ar[4] = {a4.x, a4.y, a4.z, a4.w};
            float br[4] = {b4.x, b4.y, b4.z, b4.w};
#pragma unroll
            for (int i = 0; i < 4; i++)
#pragma unroll
                for (int j = 0; j < 4; j++)
                    acc[i][j] = fmaf(ar[i], br[j], acc[i][j]);
        }
    }
#pragma unroll
    for (int i = 0; i < 4; i++) {
        float x0 = acc[i][0] + bias[n0 + tn0 + 0];
        float x1 = acc[i][1] + bias[n0 + tn0 + 1];
        float x2 = acc[i][2] + bias[n0 + tn0 + 2];
        float x3 = acc[i][3] + bias[n0 + tn0 + 3];
        __nv_bfloat162 p0 = __floats2bfloat162_rn(x0, x1);
        __nv_bfloat162 p1 = __floats2bfloat162_rn(x2, x3);
        uint2 pk;
        pk.x = *(uint32_t*)&p0;
        pk.y = *(uint32_t*)&p1;
        *(uint2*)(C + (size_t)(m0 + tm0 + i) * 256 + n0 + tn0) = pk;
    }
}

// ---- smem-staged vec-mat, 2 rows. Weights stream via double-buffered smem.
// Thread = (r, kh, g): row r=tid>>8, k-split kh, 4-col group g.
// ACT: 0 none, 1 relu, 2 sigmoid, 3 tanhf.
template<int K, int N, int CK, int KS, int ACT>
__device__ __forceinline__ void vmS(const float* __restrict__ W,
                                    const float* __restrict__ bias,
                                    const float* x0, const float* x1,
                                    float* y0, float* y1,
                                    float* wbuf, float* pbuf)
{
    constexpr int NC  = K / CK;
    static_assert(NC * CK == K, "CK must divide K");
    constexpr int CKN = CK * N;
    constexpr int NGP = 256 / KS;          // padded col-group count
    constexpr int SUB = CK / KS;
    static_assert(SUB * KS == CK, "KS must divide CK");
    constexpr int NLD = (CKN / 4 + NT - 1) / NT;

    const int tid = threadIdx.x;
    const int g   = tid % NGP;
    const int kh  = (tid / NGP) % KS;
    const int r   = tid >> 8;
    const bool active = (4 * g < N);
    const float* xr = r ? x1 : x0;
    float4* pb = (float4*)pbuf;

    float a0 = 0.f, a1 = 0.f, a2 = 0.f, a3 = 0.f;
    float4 lr[NLD];

    // prologue: fetch chunk 0 into regs
    {
        const float4* src = (const float4*)W;
#pragma unroll
        for (int i = 0; i < NLD; i++) {
            int idx = tid + i * NT;
            if (idx < CKN / 4) lr[i] = src[idx];
        }
    }

#pragma unroll 1
    for (int c = 0; c < NC; c++) {
        // store regs -> buf[c&1]
        float4* dst = (float4*)(wbuf + (c & 1) * CKN);
#pragma unroll
        for (int i = 0; i < NLD; i++) {
            int idx = tid + i * NT;
            if (idx < CKN / 4) dst[idx] = lr[i];
        }
        // issue loads for next chunk (overlap with compute below)
        if (c + 1 < NC) {
            const float4* src = (const float4*)(W + (size_t)(c + 1) * CKN);
#pragma unroll
            for (int i = 0; i < NLD; i++) {
                int idx = tid + i * NT;
                if (idx < CKN / 4) lr[i] = src[idx];
            }
        }
        __syncthreads();
        if (active) {
            const float* ws = wbuf + (c & 1) * CKN;
            const int kb = kh * SUB;
            const float* xc = xr + c * CK + kb;
#pragma unroll
            for (int kk = 0; kk < SUB; kk++) {
                float xv = xc[kk];
                float4 w = *(const float4*)&ws[(kb + kk) * N + 4 * g];
                a0 = fmaf(xv, w.x, a0);
                a1 = fmaf(xv, w.y, a1);
                a2 = fmaf(xv, w.z, a2);
                a3 = fmaf(xv, w.w, a3);
            }
        }
    }
    // combine partials across KS
    if (active) pb[(kh * 2 + r) * NGP + g] = make_float4(a0, a1, a2, a3);
    __syncthreads();
    for (int idx = tid; idx < 2 * (N / 4); idx += NT) {
        int rr2 = idx / (N / 4);
        int gg  = idx % (N / 4);
        float4 s = pb[rr2 * NGP + gg];
#pragma unroll
        for (int k2 = 1; k2 < KS; k2++) {
            float4 p = pb[(k2 * 2 + rr2) * NGP + gg];
            s.x += p.x; s.y += p.y; s.z += p.z; s.w += p.w;
        }
        float4 b4 = ((const float4*)bias)[gg];
        s.x += b4.x; s.y += b4.y; s.z += b4.z; s.w += b4.w;
        if (ACT == 1) {
            s.x = fmaxf(s.x, 0.f); s.y = fmaxf(s.y, 0.f);
            s.z = fmaxf(s.z, 0.f); s.w = fmaxf(s.w, 0.f);
        } else if (ACT == 2) {
            s.x = 1.f / (1.f + expf(-s.x)); s.y = 1.f / (1.f + expf(-s.y));
            s.z = 1.f / (1.f + expf(-s.z)); s.w = 1.f / (1.f + expf(-s.w));
        } else if (ACT == 3) {
            s.x = tanhf(s.x); s.y = tanhf(s.y);
            s.z = tanhf(s.z); s.w = tanhf(s.w);
        }
        float* yy = rr2 ? y1 : y0;
        ((float4*)yy)[gg] = s;
    }
    __syncthreads();
}

// ------------------- persistent decoder: 1 block = 2 batch rows ------------
__global__ void __launch_bounds__(NT, 1) decode_kernel(
    const float* __restrict__ enc, const int* __restrict__ mask,
    const float* __restrict__ inp_att, const float* __restrict__ style_tok,
    const float* __restrict__ pre_W1, const float* __restrict__ pre_b1,
    const float* __restrict__ pre_W2, const float* __restrict__ pre_b2,
    const float* __restrict__ att_Wg, const float* __restrict__ att_bg,
    const float* __restrict__ att_Wc, const float* __restrict__ att_bc,
    const float* __restrict__ attn_Wq, const float* __restrict__ attn_bq,
    const float* __restrict__ attn_v,
    const float* __restrict__ deci_W, const float* __restrict__ deci_b,
    const float* __restrict__ dec1_Wg, const float* __restrict__ dec1_bg,
    const float* __restrict__ dec1_Wc, const float* __restrict__ dec1_bc,
    const float* __restrict__ dec2_Wg, const float* __restrict__ dec2_bg,
    const float* __restrict__ dec2_Wc, const float* __restrict__ dec2_bc,
    const float* __restrict__ out_W, const float* __restrict__ out_b,
    float* __restrict__ seq, float* __restrict__ alph, float* __restrict__ wp)
{
    extern __shared__ float sm[];
    float (*es)[1024] = (float(*)[1024])sm;                 // 2048
    float (*xa)[640]  = (float(*)[640])(sm + 2048);         // 1280
    float (*xd)[512]  = (float(*)[512])(sm + 3328);         // 1024
    float (*x1)[512]  = (float(*)[512])(sm + 4352);         // 1024
    float (*x2)[512]  = (float(*)[512])(sm + 5376);         // 1024
    float (*tmp)[512] = (float(*)[512])(sm + 6400);         // 1024
    float (*hA)[256]  = (float(*)[256])(sm + 7424);
    float (*h1s)[256] = (float(*)[256])(sm + 7936);
    float (*h2s)[256] = (float(*)[256])(sm + 8448);
    float (*us)[256]  = (float(*)[256])(sm + 8960);
    float (*sst)[256] = (float(*)[256])(sm + 9472);
    float (*lastv)[80] = (float(*)[80])(sm + 9984);         // 160
    float* vsh = sm + 10144;                                // 256
    float (*red)[8] = (float(*)[8])(sm + 10400);            // 16
    float* pbuf = sm + 10416;                               // 2048
    float* wbuf = sm + 12464;                               // 16384 -> 28848 total

    const int tid = threadIdx.x;
    const int blk = blockIdx.x;
    const int r8 = tid >> 8;
    const int d8 = tid & 255;

    if (tid < 256) vsh[tid] = attn_v[tid];
    {
        int b = blk * 2 + r8;
        float s = 0.f;
#pragma unroll
        for (int k = 0; k < 10; k++)
            s += inp_att[b * 10 + k] * style_tok[k * 256 + d8];
        sst[r8][d8] = s;
        hA[r8][d8] = 0.f; h1s[r8][d8] = 0.f; h2s[r8][d8] = 0.f;
        xa[r8][d8] = 0.f;
        if (d8 < 80) lastv[r8][d8] = 0.f;
    }
    __syncthreads();

    const int mb0 = mask[blk * 2], mb1 = mask[blk * 2 + 1];
    const int lane = tid & 31;
    const int rr = r8;
    const int wl = (tid >> 5) & 7;
    const int lt = d8;
    const int mbr = rr ? mb1 : mb0;
    const size_t browg = (size_t)(blk * 2 + rr);

    for (int t = 0; t < TDEC; t++) {
        // S1: p1 = relu(last @ W1 + b1) -> x1[:256)
        vmS<80, 256, 16, 4, 1>(pre_W1, pre_b1, lastv[0], lastv[1], x1[0], x1[1], wbuf, pbuf);
        // S2: p = relu(p1 @ W2 + b2) -> xa[256:384)
        vmS<256, 128, 64, 8, 1>(pre_W2, pre_b2, x1[0], x1[1], xa[0] + 256, xa[1] + 256, wbuf, pbuf);
        // h_att -> xa[384:640)
        xa[r8][384 + d8] = hA[r8][d8];
        __syncthreads();
        // S3: gates = sigmoid([ctx,p,h] @ att_Wg + bg)
        vmS<640, 512, 16, 2, 2>(att_Wg, att_bg, xa[0], xa[1], tmp[0], tmp[1], wbuf, pbuf);
        xa[r8][384 + d8] = tmp[r8][d8] * hA[r8][d8];
        us[r8][d8] = tmp[r8][256 + d8];
        __syncthreads();
        // S4: c = tanh([ctx,p,r*h] @ att_Wc + bc); h_att = u*h + (1-u)*c
        vmS<640, 256, 32, 4, 3>(att_Wc, att_bc, xa[0], xa[1], tmp[0], tmp[1], wbuf, pbuf);
        {
            float u = us[r8][d8];
            float hn = u * hA[r8][d8] + (1.f - u) * tmp[r8][d8];
            hA[r8][d8] = hn;
            xd[r8][d8] = hn;
        }
        __syncthreads();
        // S5: q = h_att @ Wq + bq -> x2[:256)
        vmS<256, 256, 32, 4, 0>(attn_Wq, attn_bq, hA[0], hA[1], x2[0], x2[1], wbuf, pbuf);

        // ---- S6: attention (R12 layout: warp-per-token over keys[b][t][d]) ----
        {
            const int d0 = lane * 8;
            const float* qs = x2[rr];
            float4 qa = *(const float4*)&qs[d0];
            float4 qb = *(const float4*)&qs[d0 + 4];
            float4 va = *(const float4*)&vsh[d0];
            float4 vb = *(const float4*)&vsh[d0 + 4];
            const __nv_bfloat16* kbase = g_keys + browg * TENC * 256;
            for (int tt = wl; tt < mbr; tt += 8) {
                uint4 kv = *(const uint4*)(kbase + (size_t)tt * 256 + d0);
                float2 f0 = __bfloat1622float2(*(__nv_bfloat162*)&kv.x);
                float2 f1 = __bfloat1622float2(*(__nv_bfloat162*)&kv.y);
                float2 f2 = __bfloat1622float2(*(__nv_bfloat162*)&kv.z);
                float2 f3 = __bfloat1622float2(*(__nv_bfloat162*)&kv.w);
                float part;
                part  = tanh_fast(f0.x + qa.x) * va.x;
                part += tanh_fast(f0.y + qa.y) * va.y;
                part += tanh_fast(f1.x + qa.z) * va.z;
                part += tanh_fast(f1.y + qa.w) * va.w;
                part += tanh_fast(f2.x + qb.x) * vb.x;
                part += tanh_fast(f2.y + qb.y) * vb.y;
                part += tanh_fast(f3.x + qb.z) * vb.z;
                part += tanh_fast(f3.y + qb.w) * vb.w;
#pragma unroll
                for (int o = 16; o; o >>= 1)
                    part += __shfl_xor_sync(0xffffffffu, part, o);
                if (lane == 0) es[rr][tt] = part;
            }
            __syncthreads();
            float mx = -1e30f;
            for (int tt = lt; tt < mbr; tt += 256) mx = fmaxf(mx, es[rr][tt]);
#pragma unroll
            for (int o = 16; o; o >>= 1)
                mx = fmaxf(mx, __shfl_xor_sync(0xffffffffu, mx, o));
            if (lane == 0) red[rr][wl] = mx;
            __syncthreads();
            mx = red[rr][0];
#pragma unroll
            for (int i = 1; i < 8; i++) mx = fmaxf(mx, red[rr][i]);
            float smv = 0.f;
            for (int tt = lt; tt < mbr; tt += 256) {
                float p = __expf(es[rr][tt] - mx);
                es[rr][tt] = p;
                smv += p;
            }
#pragma unroll
            for (int o = 16; o; o >>= 1)
                smv += __shfl_xor_sync(0xffffffffu, smv, o);
            __syncthreads();
            if (lane == 0) red[rr][wl] = smv;
            __syncthreads();
            float tsum = red[rr][0];
#pragma unroll
            for (int i = 1; i < 8; i++) tsum += red[rr][i];
            float inv = 1.f / tsum;
            float* arow = alph + ((size_t)t * BATCH + browg) * 1024;
            for (int tt = lt; tt < 1024; tt += 256) {
                float a = (tt < mbr) ? es[rr][tt] * inv : 0.f;
                es[rr][tt] = a;
                arow[tt] = a;
            }
            __syncthreads();
            const float* erow = enc + browg * TENC * 256 + lt;
            float c = 0.f;
#pragma unroll 8
            for (int tt = 0; tt < mbr; tt++)
                c = fmaf(es[rr][tt], erow[(size_t)tt * 256], c);
            xa[rr][lt] = c;
            xd[rr][256 + lt] = c + sst[rr][lt];
            float as_ = fabsf(sst[rr][lt]);
            float f = as_ / (fabsf(c) + as_);
#pragma unroll
            for (int o = 16; o; o >>= 1)
                f += __shfl_xor_sync(0xffffffffu, f, o);
            __syncthreads();
            if (lane == 0) red[rr][wl] = f;
            __syncthreads();
            if (tid == 0) {
                float s = 0.f;
#pragma unroll
                for (int i = 0; i < 8; i++) s += red[0][i] + red[1][i];
                atomicAdd(wp + t, s * (1.f / (BATCH * 256.f)));
            }
            __syncthreads();
        }

        // S7: dec_in = [h_att, wctx] @ deci_W + b -> x1[:256)
        vmS<512, 256, 32, 4, 0>(deci_W, deci_b, xd[0], xd[1], x1[0], x1[1], wbuf, pbuf);
        x1[r8][256 + d8] = h1s[r8][d8];
        __syncthreads();
        // S8: dec1 gates
        vmS<512, 512, 16, 2, 2>(dec1_Wg, dec1_bg, x1[0], x1[1], tmp[0], tmp[1], wbuf, pbuf);
        x1[r8][256 + d8] = tmp[r8][d8] * h1s[r8][d8];
        us[r8][d8] = tmp[r8][256 + d8];
        __syncthreads();
        // S9: dec1 cand; h1 update; o1 = h1 + dec_in -> x2[:256)
        vmS<512, 256, 32, 4, 3>(dec1_Wc, dec1_bc, x1[0], x1[1], tmp[0], tmp[1], wbuf, pbuf);
        {
            float u = us[r8][d8];
            float hn = u * h1s[r8][d8] + (1.f - u) * tmp[r8][d8];
            h1s[r8][d8] = hn;
            x2[r8][d8] = hn + x1[r8][d8];
            x2[r8][256 + d8] = h2s[r8][d8];
        }
        __syncthreads();
        // S10: dec2 gates
        vmS<512, 512, 16, 2, 2>(dec2_Wg, dec2_bg, x2[0], x2[1], tmp[0], tmp[1], wbuf, pbuf);
        x2[r8][256 + d8] = tmp[r8][d8] * h2s[r8][d8];
        us[r8][d8] = tmp[r8][256 + d8];
        __syncthreads();
        // S11: dec2 cand; h2 update; o2 = h2 + o1 -> x1[:256)
        vmS<512, 256, 32, 4, 3>(dec2_Wc, dec2_bc, x2[0], x2[1], tmp[0], tmp[1], wbuf, pbuf);
        {
            float u = us[r8][d8];
            float hn = u * h2s[r8][d8] + (1.f - u) * tmp[r8][d8];
            h2s[r8][d8] = hn;
            x1[r8][d8] = hn + x2[r8][d8];
        }
        __syncthreads();
        // S12: dense_out = o2 @ out_W + out_b (N=400)
        vmS<256, 400, 16, 2, 0>(out_W, out_b, x1[0], x1[1], tmp[0], tmp[1], wbuf, pbuf);
        if (tid < 400) {
#pragma unroll
            for (int r = 0; r < 2; r++) {
                float v = tmp[r][tid];
                seq[(size_t)(blk * 2 + r) * (TDEC * 400) + t * 400 + tid] = v;
                if (tid >= 320) lastv[r][tid - 320] = v;
            }
        }
        __syncthreads();
    }
}

extern "C" void kernel_launch(void* const* d_in, const int* in_sizes, int n_in,
                              void* d_out, int out_size)
{
    const float* enc      = (const float*)d_in[0];
    const int*   mask     = (const int*)d_in[1];
    const float* inp_att  = (const float*)d_in[2];
    const float* style_tk = (const float*)d_in[3];
    const float* pre_W1   = (const float*)d_in[4];
    const float* pre_b1   = (const float*)d_in[5];
    const float* pre_W2   = (const float*)d_in[6];
    const float* pre_b2   = (const float*)d_in[7];
    const float* att_Wg   = (const float*)d_in[8];
    const float* att_bg   = (const float*)d_in[9];
    const float* att_Wc   = (const float*)d_in[10];
    const float* att_bc   = (const float*)d_in[11];
    const float* attn_Wk  = (const float*)d_in[12];
    const float* attn_bk  = (const float*)d_in[13];
    const float* attn_Wq  = (const float*)d_in[14];
    const float* attn_bq  = (const float*)d_in[15];
    const float* attn_v   = (const float*)d_in[16];
    const float* deci_W   = (const float*)d_in[17];
    const float* deci_b   = (const float*)d_in[18];
    const float* dec1_Wg  = (const float*)d_in[19];
    const float* dec1_bg  = (const float*)d_in[20];
    const float* dec1_Wc  = (const float*)d_in[21];
    const float* dec1_bc  = (const float*)d_in[22];
    const float* dec2_Wg  = (const float*)d_in[23];
    const float* dec2_bg  = (const float*)d_in[24];
    const float* dec2_Wc  = (const float*)d_in[25];
    const float* dec2_bc  = (const float*)d_in[26];
    const float* out_W    = (const float*)d_in[27];
    const float* out_b    = (const float*)d_in[28];

    float* out  = (float*)d_out;
    float* seq  = out;
    float* alph = out + (size_t)BATCH * TDEC * 5 * 80;
    float* wp   = alph + (size_t)TDEC * BATCH * TENC;

    __nv_bfloat16* pKeys;
    cudaGetSymbolAddress((void**)&pKeys, g_keys);

    static int smem_set = 0;
    const int smem_bytes = 28848 * 4;
    if (!smem_set) {
        cudaFuncSetAttribute(decode_kernel,
                             cudaFuncAttributeMaxDynamicSharedMemorySize, smem_bytes);
        smem_set = 1;
    }

    zero_wp<<<1, 256>>>(wp);
    keys_gemm<<<dim3(4, 2048), 256>>>(enc, attn_Wk, attn_bk, pKeys);
    decode_kernel<<<BATCH / 2, NT, smem_bytes>>>(
        enc, mask, inp_att, style_tk,
        pre_W1, pre_b1, pre_W2, pre_b2,
        att_Wg, att_bg, att_Wc, att_bc,
        attn_Wq, attn_bq, attn_v,
        deci_W, deci_b,
        dec1_Wg, dec1_bg, dec1_Wc, dec1_bc,
        dec2_Wg, dec2_bg, dec2_Wc, dec2_bc,
        out_W, out_b,
        seq, alph, wp);
}